// round 16
// baseline (speedup 1.0000x reference)
#include <cuda_runtime.h>
#include <cuda_fp16.h>
#include <math.h>
#include <stdint.h>

// ---------------- problem constants ----------------
#define HIDDEN 3584
#define NQ 28
#define NKV 4
#define DH 128
#define QSZ (NQ*DH)            // 3584
#define KVSZ (NKV*DH)          // 512
#define NQKV (QSZ + 2*KVSZ)    // 4608
#define BATCH 2
#define SEQ 2048
#define MROWS (BATCH*SEQ)      // 4096
#define GQA (NQ/NKV)           // 7
#define ATT_SCALE 0.08838834764831845f
#define C_SCALE (ATT_SCALE * 1.4426950408889634f)   // scale * log2(e)

// ---------------- scratch ----------------
__device__ __half g_qkvh[(size_t)MROWS * NQKV];        // qkv fp16

__device__ __half g_A[(size_t)MROWS * HIDDEN];         // hidden fp16
__device__ __half g_WqkvT[(size_t)NQKV * HIDDEN];      // Wqkv^T fp16
__device__ __half g_WoT[(size_t)HIDDEN * QSZ];         // Wo^T fp16
__device__ __half g_O[(size_t)MROWS * QSZ];            // attn out fp16

__device__ __half g_Qh[(size_t)BATCH * NQ * SEQ * DH];
__device__ __half g_Kh[(size_t)BATCH * NKV * SEQ * DH];
__device__ __half g_Vh[(size_t)BATCH * NKV * SEQ * DH];

__device__ float g_freq[64];                           // rope inv freqs
__device__ float g_cos[(size_t)MROWS * 64];            // rope tables
__device__ float g_sin[(size_t)MROWS * 64];

// ---------------- PTX helpers ----------------
__device__ __forceinline__ uint32_t smem_to_u32(const void* p) {
    uint32_t a;
    asm("{ .reg .u64 t; cvta.to.shared.u64 t, %1; cvt.u32.u64 %0, t; }" : "=r"(a) : "l"(p));
    return a;
}
#define CP_ASYNC_16(dst, src) \
    asm volatile("cp.async.cg.shared.global [%0], [%1], 16;" :: "r"(dst), "l"(src))
#define CP_ASYNC_COMMIT() asm volatile("cp.async.commit_group;" ::: "memory")
#define CP_ASYNC_WAIT1()  asm volatile("cp.async.wait_group 1;" ::: "memory")
#define CP_ASYNC_WAIT2()  asm volatile("cp.async.wait_group 2;" ::: "memory")
#define CP_ASYNC_WAIT3()  asm volatile("cp.async.wait_group 3;" ::: "memory")
#define LDSM_X4(r0,r1,r2,r3, addr) \
    asm volatile("ldmatrix.sync.aligned.m8n8.x4.shared.b16 {%0,%1,%2,%3}, [%4];" \
        : "=r"(r0),"=r"(r1),"=r"(r2),"=r"(r3) : "r"(addr))
#define LDSM_X4T(r0,r1,r2,r3, addr) \
    asm volatile("ldmatrix.sync.aligned.m8n8.x4.trans.shared.b16 {%0,%1,%2,%3}, [%4];" \
        : "=r"(r0),"=r"(r1),"=r"(r2),"=r"(r3) : "r"(addr))
#define MMA_F16(ac, a, b0v, b1v) \
    asm volatile("mma.sync.aligned.m16n8k16.row.col.f32.f16.f16.f32 " \
        "{%0,%1,%2,%3}, {%4,%5,%6,%7}, {%8,%9}, {%0,%1,%2,%3};" \
        : "+f"((ac)[0]),"+f"((ac)[1]),"+f"((ac)[2]),"+f"((ac)[3]) \
        : "r"((a)[0]),"r"((a)[1]),"r"((a)[2]),"r"((a)[3]),"r"(b0v),"r"(b1v))

// fast exp2 on FMA pipe, ~2.4e-6 abs err, no MUFU; clamps at -120 (mask path)
__device__ __forceinline__ float fexp2(float x) {
    x = fmaxf(x, -120.f);
    float z = x + 12582912.f;
    int   ni = __float_as_int(z);
    float f  = x - (z - 12582912.f);
    float p  = 1.33335581e-3f;
    p = fmaf(p, f, 9.61812911e-3f);
    p = fmaf(p, f, 5.55041087e-2f);
    p = fmaf(p, f, 2.40226507e-1f);
    p = fmaf(p, f, 6.93147181e-1f);
    p = fmaf(p, f, 1.0f);
    return __int_as_float(__float_as_int(p) + (ni << 23));
}

// ---------------- prep: fp32 -> fp16 convert ----------------
__global__ __launch_bounds__(256) void convert_fp32_v4(
    const float4* __restrict__ in, __half2* __restrict__ out, int n4)
{
    int i = blockIdx.x * 256 + threadIdx.x;
    if (i >= n4) return;
    float4 v = in[i];
    out[i*2]   = __floats2half2_rn(v.x, v.y);
    out[i*2+1] = __floats2half2_rn(v.z, v.w);
}

// ---------------- prep: transpose fp32 [R,C] -> fp16 [C,R] ----------------
__global__ __launch_bounds__(256) void transpose_h(
    const float* __restrict__ in, __half* __restrict__ outH, int R, int C)
{
    __shared__ float t[32][33];
    const int tx = threadIdx.x & 31, ty = threadIdx.x >> 5;
    const int r0 = blockIdx.y * 32, c0 = blockIdx.x * 32;
    #pragma unroll
    for (int j = 0; j < 4; j++) {
        int r = r0 + ty + j*8;
        t[ty + j*8][tx] = in[(size_t)r * C + c0 + tx];
    }
    __syncthreads();
    #pragma unroll
    for (int j = 0; j < 4; j++) {
        int c = c0 + ty + j*8;
        int r = r0 + tx;
        outH[(size_t)c * R + r] = __float2half_rn(t[tx][ty + j*8]);
    }
}

// ---------------- persistent fp16 GEMM via mma.sync (5-stage, 2 CTAs/SM) -------
#define GKC 32
#define LDT 40
#define TILEB (128 * LDT * 2)         // 10240 B
#define STAGEB (2 * TILEB)            // A, B = 20480 B
#define NSTAGE 5
#define GEMM_SMEM (NSTAGE * STAGEB)   // 102400 -> 2 CTAs/SM
#define GEMM_GRID 296                 // 2 x 148 SMs

__device__ __forceinline__ void store2(float* p, float a, float b) {
    *(float2*)p = make_float2(a, b);
}
__device__ __forceinline__ void store2(__half* p, float a, float b) {
    __half2 h = __floats2half2_rn(a, b);
    *(__half2*)p = h;
}

__device__ __forceinline__ void issue_chunk(
    const __half* const* basep, int K, int k0, uint32_t stage_u32, int tid)
{
    #pragma unroll
    for (int t = 0; t < 2; t++) {
        const __half* bp = basep[t] + k0;
        const uint32_t dst0 = stage_u32 + t * TILEB;
        #pragma unroll
        for (int i = tid; i < 512; i += 256) {
            const int row = i >> 2, ch = i & 3;
            const uint32_t dst = dst0 + row * (LDT*2) + ch * 16;
            const char* src = (const char*)(bp + (size_t)row * K) + ch * 16;
            CP_ASYNC_16(dst, src);
        }
    }
}

template <typename TO>
__global__ __launch_bounds__(256, 2) void gemm_f16(
    const __half* __restrict__ A, const __half* __restrict__ B,
    const float* __restrict__ bias, TO* __restrict__ C,
    int M, int N, int K, int nbx, int ntiles)
{
    extern __shared__ char smem[];
    const uint32_t sbase = smem_to_u32(smem);
    const int tid  = threadIdx.x;
    const int wid  = tid >> 5;
    const int lane = tid & 31;
    const int wm = wid & 1;
    const int wn = wid >> 1;
    const int nc = K / GKC;

    const uint32_t aOff = (uint32_t)((wm*64 + (lane & 15)) * (LDT*2) + (lane >> 4) * 16);
    const uint32_t bOff = (uint32_t)(TILEB +
        (wn*32 + (lane & 7) + ((lane >> 4) << 3)) * (LDT*2) + (((lane >> 3) & 1) * 16));

    for (int t = blockIdx.x; t < ntiles; t += gridDim.x) {
        const int m0 = (t / nbx) * 128;
        const int n0 = (t % nbx) * 128;
        __syncthreads();   // protect smem reuse across tile iterations

        const __half* basep[2];
        basep[0] = A + (size_t)m0 * K;
        basep[1] = B + (size_t)n0 * K;

        float acc[4][4][4];
        #pragma unroll
        for (int mi = 0; mi < 4; mi++)
            #pragma unroll
            for (int ni = 0; ni < 4; ni++)
                #pragma unroll
                for (int j = 0; j < 4; j++) acc[mi][ni][j] = 0.f;

        issue_chunk(basep, K, 0, sbase, tid);
        CP_ASYNC_COMMIT();
        issue_chunk(basep, K, GKC, sbase + STAGEB, tid);
        CP_ASYNC_COMMIT();
        issue_chunk(basep, K, 2*GKC, sbase + 2*STAGEB, tid);
        CP_ASYNC_COMMIT();
        issue_chunk(basep, K, 3*GKC, sbase + 3*STAGEB, tid);
        CP_ASYNC_COMMIT();

        for (int c = 0; c < nc; c++) {
            CP_ASYNC_WAIT3();
            __syncthreads();
            if (c + 4 < nc)
                issue_chunk(basep, K, (c + 4) * GKC, sbase + ((c + 4) % NSTAGE) * STAGEB, tid);
            CP_ASYNC_COMMIT();

            const uint32_t st = sbase + (c % NSTAGE) * STAGEB;
            #pragma unroll
            for (int ks = 0; ks < 2; ks++) {
                const uint32_t kb = ks * 32;
                uint32_t af[4][4], bf[2][4];
                #pragma unroll
                for (int mi = 0; mi < 4; mi++) {
                    const uint32_t ah = st + aOff + mi * 16 * (LDT*2) + kb;
                    LDSM_X4(af[mi][0], af[mi][1], af[mi][2], af[mi][3], ah);
                }
                #pragma unroll
                for (int p = 0; p < 2; p++) {
                    const uint32_t bh = st + bOff + p * 16 * (LDT*2) + kb;
                    LDSM_X4(bf[p][0], bf[p][1], bf[p][2], bf[p][3], bh);
                }
                #pragma unroll
                for (int mi = 0; mi < 4; mi++)
                    #pragma unroll
                    for (int ni = 0; ni < 4; ni++) {
                        const int p = ni >> 1, q = (ni & 1) << 1;
                        MMA_F16(acc[mi][ni], af[mi], bf[p][q], bf[p][q+1]);
                    }
            }
        }

        #pragma unroll
        for (int mi = 0; mi < 4; mi++) {
            const int r0 = m0 + wm*64 + mi*16 + (lane >> 2);
            #pragma unroll
            for (int ni = 0; ni < 4; ni++) {
                const int c0 = n0 + wn*32 + ni*8 + (lane & 3)*2;
                float b0 = 0.f, b1 = 0.f;
                if (bias) { b0 = bias[c0]; b1 = bias[c0 + 1]; }
                store2(C + (size_t)r0 * N + c0,       acc[mi][ni][0] + b0, acc[mi][ni][1] + b1);
                store2(C + (size_t)(r0 + 8) * N + c0, acc[mi][ni][2] + b0, acc[mi][ni][3] + b1);
            }
        }
    }
}

// ---------------- rope freq table: 64 fp64 pows total ----------------
__global__ void freq_init()
{
    int i = threadIdx.x;
    if (i < 64)
        g_freq[i] = (float)pow(10000.0, -(double)(2*i) / 128.0);
}

// ---------------- rope tables: one sincos per distinct (bs, i) ----------------
__global__ __launch_bounds__(256) void build_rope_table(const int* __restrict__ pos)
{
    int idx = blockIdx.x * 256 + threadIdx.x;
    if (idx >= MROWS * 64) return;
    const int bs = idx >> 6, i = idx & 63;
    float sv, cv;
    sincosf((float)pos[bs] * g_freq[i], &sv, &cv);
    g_cos[idx] = cv;
    g_sin[idx] = sv;
}

// ---------------- RoPE apply + head split (8 pairs/thread) ----------------
__global__ __launch_bounds__(256) void rope_apply()
{
    const int total = MROWS * 36 * 8;
    int idx = blockIdx.x * 256 + threadIdx.x;
    if (idx >= total) return;
    const int i8 = idx & 7;
    const int h  = (idx >> 3) % 36;
    const int bs = idx / (36 * 8);
    const int b  = bs >> 11;
    const int s  = bs & 2047;
    const int i0 = i8 * 8;

    const __half* row = g_qkvh + (size_t)bs * NQKV + h * DH;
    uint4 xa = *(const uint4*)(row + i0);        // 8 halves: x1
    uint4 xb = *(const uint4*)(row + i0 + 64);   // 8 halves: x2
    float x1[8], x2[8];
    {
        const __half2* pa = reinterpret_cast<const __half2*>(&xa);
        const __half2* pb = reinterpret_cast<const __half2*>(&xb);
        #pragma unroll
        for (int j = 0; j < 4; j++) {
            x1[2*j]   = __low2float(pa[j]);  x1[2*j+1] = __high2float(pa[j]);
            x2[2*j]   = __low2float(pb[j]);  x2[2*j+1] = __high2float(pb[j]);
        }
    }

    float o1[8], o2[8];
    if (h < 32) {
        const float4 cv0 = *(const float4*)(g_cos + (size_t)bs*64 + i0);
        const float4 cv1 = *(const float4*)(g_cos + (size_t)bs*64 + i0 + 4);
        const float4 sv0 = *(const float4*)(g_sin + (size_t)bs*64 + i0);
        const float4 sv1 = *(const float4*)(g_sin + (size_t)bs*64 + i0 + 4);
        const float c[8]  = {cv0.x, cv0.y, cv0.z, cv0.w, cv1.x, cv1.y, cv1.z, cv1.w};
        const float sn[8] = {sv0.x, sv0.y, sv0.z, sv0.w, sv1.x, sv1.y, sv1.z, sv1.w};
        #pragma unroll
        for (int j = 0; j < 8; j++) {
            o1[j] = x1[j]*c[j] - x2[j]*sn[j];
            o2[j] = x2[j]*c[j] + x1[j]*sn[j];
        }
    } else {
        #pragma unroll
        for (int j = 0; j < 8; j++) { o1[j] = x1[j]; o2[j] = x2[j]; }
    }

    __half* dst;
    if (h < NQ)      dst = g_Qh + ((size_t)(b*NQ  + h)        * SEQ + s) * DH;
    else if (h < 32) dst = g_Kh + ((size_t)(b*NKV + (h - NQ)) * SEQ + s) * DH;
    else             dst = g_Vh + ((size_t)(b*NKV + (h - 32)) * SEQ + s) * DH;

    uint4 oa, ob;
    uint32_t* wa = reinterpret_cast<uint32_t*>(&oa);
    uint32_t* wb = reinterpret_cast<uint32_t*>(&ob);
    #pragma unroll
    for (int j = 0; j < 4; j++) {
        __half2 t1 = __floats2half2_rn(o1[2*j], o1[2*j+1]);
        __half2 t2 = __floats2half2_rn(o2[2*j], o2[2*j+1]);
        wa[j] = *reinterpret_cast<uint32_t*>(&t1);
        wb[j] = *reinterpret_cast<uint32_t*>(&t2);
    }
    *(uint4*)(dst + i0)      = oa;
    *(uint4*)(dst + i0 + 64) = ob;
}

// ---------------- tensor-core flash attention (KV tile 128) ----------------
#define FPITCH_B 272
#define Q_BYTES (128 * FPITCH_B)             // 34816
#define KVROWS 128
#define KVT_BYTES (KVROWS * FPITCH_B)        // 34816
#define KVBUF (2 * KVT_BYTES)                // K, V = 69632
#define FLASH_SMEM (Q_BYTES + 2*KVBUF)       // 174080 -> 1 CTA/SM

__device__ __forceinline__ void issue_kv(uint32_t dstbase,
    const __half* Kh, const __half* Vh, int kt, int tid)
{
    const size_t off = (size_t)kt * KVROWS * DH;
    const char* s0 = (const char*)(Kh + off);
    const char* s1 = (const char*)(Vh + off);
    #pragma unroll
    for (int i = tid; i < 2048; i += 256) {
        const int row = i >> 4, ch = i & 15;
        const uint32_t d = dstbase + row * FPITCH_B + ch * 16;
        const int soff = row * 256 + ch * 16;
        CP_ASYNC_16(d,             s0 + soff);
        CP_ASYNC_16(d + KVT_BYTES, s1 + soff);
    }
}

__global__ __launch_bounds__(256, 1) void flash_mma()
{
    extern __shared__ char fsm[];
    const uint32_t sb = smem_to_u32(fsm);
    const int tid = threadIdx.x, wid = tid >> 5, lane = tid & 31;
    const int qt = (int)gridDim.x - 1 - (int)blockIdx.x;
    const int h = blockIdx.y, b = blockIdx.z;
    const int kvh = h / GQA;
    const int qbase = qt * 128;

    const __half* Qh_g = g_Qh + ((size_t)(b*NQ + h)*SEQ + qbase)*DH;
    const size_t kvoff = (size_t)(b*NKV + kvh)*SEQ*DH;
    const __half* Kh_g = g_Kh + kvoff;
    const __half* Vh_g = g_Vh + kvoff;

    #pragma unroll
    for (int i = tid; i < 2048; i += 256) {
        const int row = i >> 4, ch = i & 15;
        CP_ASYNC_16(sb + row * FPITCH_B + ch * 16,
                    (const char*)(Qh_g + (size_t)row * DH) + ch * 16);
    }
    CP_ASYNC_COMMIT();

    const int nkt = qt + 1;
    issue_kv(sb + Q_BYTES, Kh_g, Vh_g, 0, tid);
    CP_ASYNC_COMMIT();
    if (nkt > 1)
        issue_kv(sb + Q_BYTES + KVBUF, Kh_g, Vh_g, 1, tid);
    CP_ASYNC_COMMIT();

    const uint32_t aoff = (uint32_t)((wid*16 + (lane & 15)) * FPITCH_B + (lane >> 4) * 16);
    uint32_t qf[8][4];
    CP_ASYNC_WAIT2();
    __syncthreads();
    #pragma unroll
    for (int ks = 0; ks < 8; ks++) {
        const uint32_t qa = sb + aoff + ks * 32;
        LDSM_X4(qf[ks][0], qf[ks][1], qf[ks][2], qf[ks][3], qa);
    }

    float oacc[16][4];
    #pragma unroll
    for (int nn = 0; nn < 16; nn++)
        #pragma unroll
        for (int j = 0; j < 4; j++) oacc[nn][j] = 0.f;
    float l0 = 0.f, l1 = 0.f;

    const uint32_t boff = (uint32_t)(((lane & 7) + ((lane >> 4) << 3)) * FPITCH_B + ((lane >> 3) & 1) * 16);
    const uint32_t voff = (uint32_t)((lane & 15) * FPITCH_B + (lane >> 4) * 16);
    const int gr0 = qbase + wid*16 + (lane >> 2);
    const int gr1 = gr0 + 8;

    for (int kt = 0; kt < nkt; kt++) {
        CP_ASYNC_WAIT1();
        __syncthreads();
        const uint32_t kb = sb + Q_BYTES + (kt & 1) * KVBUF;

        float sacc[16][4];
        #pragma unroll
        for (int j = 0; j < 16; j++)
            #pragma unroll
            for (int e = 0; e < 4; e++) sacc[j][e] = 0.f;

        #pragma unroll
        for (int ks = 0; ks < 8; ks++) {
            #pragma unroll
            for (int jj = 0; jj < 8; jj++) {
                uint32_t bh[4];
                const uint32_t ka = kb + boff + jj * (16 * FPITCH_B) + ks * 32;
                LDSM_X4(bh[0], bh[1], bh[2], bh[3], ka);
                MMA_F16(sacc[2*jj],   qf[ks], bh[0], bh[1]);
                MMA_F16(sacc[2*jj+1], qf[ks], bh[2], bh[3]);
            }
        }

        if (kt == nkt - 1) {
            #pragma unroll
            for (int j = 0; j < 16; j++) {
                const int c0 = kt*KVROWS + j*8 + (lane & 3)*2;
                sacc[j][0] = (c0     > gr0) ? -1e9f : sacc[j][0] * C_SCALE;
                sacc[j][1] = (c0 + 1 > gr0) ? -1e9f : sacc[j][1] * C_SCALE;
                sacc[j][2] = (c0     > gr1) ? -1e9f : sacc[j][2] * C_SCALE;
                sacc[j][3] = (c0 + 1 > gr1) ? -1e9f : sacc[j][3] * C_SCALE;
            }
        } else {
            #pragma unroll
            for (int j = 0; j < 16; j++)
                #pragma unroll
                for (int e = 0; e < 4; e++) sacc[j][e] *= C_SCALE;
        }

        #pragma unroll
        for (int j = 0; j < 16; j++) {
            float p0 = fexp2(sacc[j][0]);
            float p1 = fexp2(sacc[j][1]);
            float p2 = fexp2(sacc[j][2]);
            float p3 = fexp2(sacc[j][3]);
            sacc[j][0] = p0; sacc[j][1] = p1; sacc[j][2] = p2; sacc[j][3] = p3;
            l0 += p0 + p1; l1 += p2 + p3;
        }

        #pragma unroll
        for (int kp = 0; kp < 8; kp++) {
            uint32_t pa[4];
            __half2 t0 = __floats2half2_rn(sacc[2*kp][0],   sacc[2*kp][1]);
            __half2 t1 = __floats2half2_rn(sacc[2*kp][2],   sacc[2*kp][3]);
            __half2 t2 = __floats2half2_rn(sacc[2*kp+1][0], sacc[2*kp+1][1]);
            __half2 t3 = __floats2half2_rn(sacc[2*kp+1][2], sacc[2*kp+1][3]);
            pa[0] = *reinterpret_cast<uint32_t*>(&t0);
            pa[1] = *reinterpret_cast<uint32_t*>(&t1);
            pa[2] = *reinterpret_cast<uint32_t*>(&t2);
            pa[3] = *reinterpret_cast<uint32_t*>(&t3);
            #pragma unroll
            for (int nj = 0; nj < 8; nj++) {
                uint32_t vh[4];
                const uint32_t va = kb + KVT_BYTES + voff + kp * (16 * FPITCH_B) + nj * 32;
                LDSM_X4T(vh[0], vh[1], vh[2], vh[3], va);
                MMA_F16(oacc[2*nj],   pa, vh[0], vh[1]);
                MMA_F16(oacc[2*nj+1], pa, vh[2], vh[3]);
            }
        }

        __syncthreads();
        if (kt + 2 < nkt)
            issue_kv(sb + Q_BYTES + (kt & 1) * KVBUF, Kh_g, Vh_g, kt + 2, tid);
        CP_ASYNC_COMMIT();
    }

    l0 += __shfl_xor_sync(0xffffffffu, l0, 1);
    l0 += __shfl_xor_sync(0xffffffffu, l0, 2);
    l1 += __shfl_xor_sync(0xffffffffu, l1, 1);
    l1 += __shfl_xor_sync(0xffffffffu, l1, 2);
    const float inv0 = 1.f / l0;
    const float inv1 = 1.f / l1;
    const size_t rbase0 = (size_t)(b*SEQ + gr0) * QSZ + h*DH;
    const size_t rbase1 = (size_t)(b*SEQ + gr1) * QSZ + h*DH;
    #pragma unroll
    for (int nn = 0; nn < 16; nn++) {
        const int col = nn*8 + (lane & 3)*2;
        __half2 o0 = __floats2half2_rn(oacc[nn][0]*inv0, oacc[nn][1]*inv0);
        __half2 o1 = __floats2half2_rn(oacc[nn][2]*inv1, oacc[nn][3]*inv1);
        *(uint32_t*)(g_O + rbase0 + col) = *reinterpret_cast<uint32_t*>(&o0);
        *(uint32_t*)(g_O + rbase1 + col) = *reinterpret_cast<uint32_t*>(&o1);
    }
}

// ---------------- launcher ----------------
extern "C" void kernel_launch(void* const* d_in, const int* in_sizes, int n_in,
                              void* d_out, int out_size)
{
    const int*   positions = (const int*)  d_in[0];
    const float* hidden    = (const float*)d_in[1];
    const float* Wqkv      = (const float*)d_in[2];
    const float* bqkv      = (const float*)d_in[3];
    const float* Wo        = (const float*)d_in[4];
    float* out = (float*)d_out;

    __half *qkvh_p, *a_p, *wq, *wo, *o_p;
    cudaGetSymbolAddress((void**)&qkvh_p, g_qkvh);
    cudaGetSymbolAddress((void**)&a_p, g_A);
    cudaGetSymbolAddress((void**)&wq,  g_WqkvT);
    cudaGetSymbolAddress((void**)&wo,  g_WoT);
    cudaGetSymbolAddress((void**)&o_p, g_O);

    cudaFuncSetAttribute(gemm_f16<__half>, cudaFuncAttributeMaxDynamicSharedMemorySize, GEMM_SMEM);
    cudaFuncSetAttribute(gemm_f16<float>,  cudaFuncAttributeMaxDynamicSharedMemorySize, GEMM_SMEM);
    cudaFuncSetAttribute(flash_mma, cudaFuncAttributeMaxDynamicSharedMemorySize, FLASH_SMEM);

    // prep
    freq_init<<<1, 64>>>();
    {
        int n4 = (MROWS * HIDDEN) / 4;
        convert_fp32_v4<<<(n4 + 255)/256, 256>>>(
            (const float4*)hidden, (__half2*)a_p, n4);
    }
    transpose_h<<<dim3(NQKV/32, HIDDEN/32), 256>>>(Wqkv, wq, HIDDEN, NQKV);
    transpose_h<<<dim3(HIDDEN/32, QSZ/32),  256>>>(Wo,   wo, QSZ, HIDDEN);
    build_rope_table<<<(MROWS*64 + 255)/256, 256>>>(positions);

    // 1) QKV projection + bias -> fp16 (persistent)
    {
        const int nbx = NQKV/128, ntiles = (MROWS/128) * nbx;   // 36 x 32 = 1152
        gemm_f16<__half><<<GEMM_GRID, 256, GEMM_SMEM>>>(
            a_p, wq, bqkv, qkvh_p, MROWS, NQKV, HIDDEN, nbx, ntiles);
    }

    // 2) RoPE apply (table-based) + head split
    {
        const int total = MROWS * 36 * 8;
        rope_apply<<<(total + 255)/256, 256>>>();
    }

    // 3) tensor-core causal flash attention (writes g_O fp16)
    flash_mma<<<dim3(SEQ/128, NQ, BATCH), 256, FLASH_SMEM>>>();

    // 4) output projection -> fp32 out (persistent)
    {
        const int nbx = HIDDEN/128, ntiles = (MROWS/128) * nbx; // 28 x 32 = 896
        gemm_f16<float><<<GEMM_GRID, 256, GEMM_SMEM>>>(
            o_p, wo, (const float*)nullptr, out, MROWS, HIDDEN, QSZ, nbx, ntiles);
    }
}

// round 17
// speedup vs baseline: 1.0292x; 1.0292x over previous
#include <cuda_runtime.h>
#include <cuda_fp16.h>
#include <math.h>
#include <stdint.h>

// ---------------- problem constants ----------------
#define HIDDEN 3584
#define NQ 28
#define NKV 4
#define DH 128
#define QSZ (NQ*DH)            // 3584
#define KVSZ (NKV*DH)          // 512
#define NQKV (QSZ + 2*KVSZ)    // 4608
#define BATCH 2
#define SEQ 2048
#define MROWS (BATCH*SEQ)      // 4096
#define GQA (NQ/NKV)           // 7
#define ATT_SCALE 0.08838834764831845f
#define C_SCALE (ATT_SCALE * 1.4426950408889634f)   // scale * log2(e)

// ---------------- scratch ----------------
__device__ __half g_qkvh[(size_t)MROWS * NQKV];        // qkv fp16

__device__ __half g_A[(size_t)MROWS * HIDDEN];         // hidden fp16
__device__ __half g_WqkvT[(size_t)NQKV * HIDDEN];      // Wqkv^T fp16
__device__ __half g_WoT[(size_t)HIDDEN * QSZ];         // Wo^T fp16
__device__ __half g_O[(size_t)MROWS * QSZ];            // attn out fp16

__device__ __half g_Qh[(size_t)BATCH * NQ * SEQ * DH];
__device__ __half g_Kh[(size_t)BATCH * NKV * SEQ * DH];
__device__ __half g_Vh[(size_t)BATCH * NKV * SEQ * DH];

__device__ float g_freq[64];                           // rope inv freqs
__device__ float g_cos[(size_t)MROWS * 64];            // rope tables
__device__ float g_sin[(size_t)MROWS * 64];

// ---------------- PTX helpers ----------------
__device__ __forceinline__ uint32_t smem_to_u32(const void* p) {
    uint32_t a;
    asm("{ .reg .u64 t; cvta.to.shared.u64 t, %1; cvt.u32.u64 %0, t; }" : "=r"(a) : "l"(p));
    return a;
}
#define CP_ASYNC_16(dst, src) \
    asm volatile("cp.async.cg.shared.global [%0], [%1], 16;" :: "r"(dst), "l"(src))
#define CP_ASYNC_COMMIT() asm volatile("cp.async.commit_group;" ::: "memory")
#define CP_ASYNC_WAIT1()  asm volatile("cp.async.wait_group 1;" ::: "memory")
#define CP_ASYNC_WAIT2()  asm volatile("cp.async.wait_group 2;" ::: "memory")
#define CP_ASYNC_WAIT3()  asm volatile("cp.async.wait_group 3;" ::: "memory")
#define LDSM_X4(r0,r1,r2,r3, addr) \
    asm volatile("ldmatrix.sync.aligned.m8n8.x4.shared.b16 {%0,%1,%2,%3}, [%4];" \
        : "=r"(r0),"=r"(r1),"=r"(r2),"=r"(r3) : "r"(addr))
#define LDSM_X4T(r0,r1,r2,r3, addr) \
    asm volatile("ldmatrix.sync.aligned.m8n8.x4.trans.shared.b16 {%0,%1,%2,%3}, [%4];" \
        : "=r"(r0),"=r"(r1),"=r"(r2),"=r"(r3) : "r"(addr))
#define MMA_F16(ac, a, b0v, b1v) \
    asm volatile("mma.sync.aligned.m16n8k16.row.col.f32.f16.f16.f32 " \
        "{%0,%1,%2,%3}, {%4,%5,%6,%7}, {%8,%9}, {%0,%1,%2,%3};" \
        : "+f"((ac)[0]),"+f"((ac)[1]),"+f"((ac)[2]),"+f"((ac)[3]) \
        : "r"((a)[0]),"r"((a)[1]),"r"((a)[2]),"r"((a)[3]),"r"(b0v),"r"(b1v))

// fast exp2 on FMA pipe, ~2.4e-6 abs err, no MUFU; clamps at -120 (mask path)
__device__ __forceinline__ float fexp2(float x) {
    x = fmaxf(x, -120.f);
    float z = x + 12582912.f;
    int   ni = __float_as_int(z);
    float f  = x - (z - 12582912.f);
    float p  = 1.33335581e-3f;
    p = fmaf(p, f, 9.61812911e-3f);
    p = fmaf(p, f, 5.55041087e-2f);
    p = fmaf(p, f, 2.40226507e-1f);
    p = fmaf(p, f, 6.93147181e-1f);
    p = fmaf(p, f, 1.0f);
    return __int_as_float(__float_as_int(p) + (ni << 23));
}

// ---------------- rope freq table: 64 fp64 pows total ----------------
__global__ void freq_init()
{
    int i = threadIdx.x;
    if (i < 64)
        g_freq[i] = (float)pow(10000.0, -(double)(2*i) / 128.0);
}

// ---------------- fused prep: convert + 2 transposes + rope table ----------------
// block ranges: [0, CONVB) convert hidden; [CONVB, +TQB) transpose Wqkv;
// [.., +TOB) transpose Wo; [.., +RTB) rope table.
#define CONVB ((MROWS*HIDDEN/4)/256)       // 14336
#define TQ_BX (NQKV/32)                    // 144
#define TQB   (TQ_BX * (HIDDEN/32))        // 16128
#define TO_BX (HIDDEN/32)                  // 112
#define TOB   (TO_BX * (QSZ/32))           // 12544
#define RTB   ((MROWS*64)/256)             // 1024
#define PREP_BLOCKS (CONVB + TQB + TOB + RTB)

__device__ __forceinline__ void transpose_body(
    const float* __restrict__ in, __half* __restrict__ outH,
    int R, int C, int bx, int by, float* t /*[32][33]*/)
{
    const int tx = threadIdx.x & 31, ty = threadIdx.x >> 5;
    const int r0 = by * 32, c0 = bx * 32;
    #pragma unroll
    for (int j = 0; j < 4; j++) {
        int r = r0 + ty + j*8;
        t[(ty + j*8)*33 + tx] = in[(size_t)r * C + c0 + tx];
    }
    __syncthreads();
    #pragma unroll
    for (int j = 0; j < 4; j++) {
        int c = c0 + ty + j*8;
        int r = r0 + tx;
        outH[(size_t)c * R + r] = __float2half_rn(t[tx*33 + (ty + j*8)]);
    }
}

__global__ __launch_bounds__(256) void prep_fused(
    const float4* __restrict__ hidden4, __half2* __restrict__ a2,
    const float* __restrict__ Wqkv, __half* __restrict__ wqT,
    const float* __restrict__ Wo,   __half* __restrict__ woT,
    const int* __restrict__ pos)
{
    __shared__ float t[32*33];
    int bid = blockIdx.x;
    if (bid < CONVB) {
        int i = bid * 256 + threadIdx.x;
        float4 v = hidden4[i];
        a2[i*2]   = __floats2half2_rn(v.x, v.y);
        a2[i*2+1] = __floats2half2_rn(v.z, v.w);
    } else if (bid < CONVB + TQB) {
        int tb = bid - CONVB;
        transpose_body(Wqkv, wqT, HIDDEN, NQKV, tb % TQ_BX, tb / TQ_BX, t);
    } else if (bid < CONVB + TQB + TOB) {
        int tb = bid - CONVB - TQB;
        transpose_body(Wo, woT, QSZ, HIDDEN, tb % TO_BX, tb / TO_BX, t);
    } else {
        int idx = (bid - CONVB - TQB - TOB) * 256 + threadIdx.x;
        const int bs = idx >> 6, i = idx & 63;
        float sv, cv;
        sincosf((float)pos[bs] * g_freq[i], &sv, &cv);
        g_cos[idx] = cv;
        g_sin[idx] = sv;
    }
}

// ---------------- fp16 GEMM via mma.sync (5-stage, 2 CTAs/SM) ----------------
#define GKC 32
#define LDT 40
#define TILEB (128 * LDT * 2)         // 10240 B
#define STAGEB (2 * TILEB)            // A, B = 20480 B
#define NSTAGE 5
#define GEMM_SMEM (NSTAGE * STAGEB)   // 102400 -> 2 CTAs/SM

__device__ __forceinline__ void store2(float* p, float a, float b) {
    *(float2*)p = make_float2(a, b);
}
__device__ __forceinline__ void store2(__half* p, float a, float b) {
    __half2 h = __floats2half2_rn(a, b);
    *(__half2*)p = h;
}

__device__ __forceinline__ void issue_chunk(
    const __half* const* basep, int K, int k0, uint32_t stage_u32, int tid)
{
    #pragma unroll
    for (int t = 0; t < 2; t++) {
        const __half* bp = basep[t] + k0;
        const uint32_t dst0 = stage_u32 + t * TILEB;
        #pragma unroll
        for (int i = tid; i < 512; i += 256) {
            const int row = i >> 2, ch = i & 3;
            const uint32_t dst = dst0 + row * (LDT*2) + ch * 16;
            const char* src = (const char*)(bp + (size_t)row * K) + ch * 16;
            CP_ASYNC_16(dst, src);
        }
    }
}

template <typename TO>
__global__ __launch_bounds__(256, 2) void gemm_f16(
    const __half* __restrict__ A, const __half* __restrict__ B,
    const float* __restrict__ bias, TO* __restrict__ C, int M, int N, int K)
{
    extern __shared__ char smem[];
    const uint32_t sbase = smem_to_u32(smem);
    const int tid  = threadIdx.x;
    const int wid  = tid >> 5;
    const int lane = tid & 31;
    const int wm = wid & 1;
    const int wn = wid >> 1;
    const int m0 = blockIdx.y * 128;
    const int n0 = blockIdx.x * 128;

    const __half* basep[2];
    basep[0] = A + (size_t)m0 * K;
    basep[1] = B + (size_t)n0 * K;

    float acc[4][4][4];
    #pragma unroll
    for (int mi = 0; mi < 4; mi++)
        #pragma unroll
        for (int ni = 0; ni < 4; ni++)
            #pragma unroll
            for (int j = 0; j < 4; j++) acc[mi][ni][j] = 0.f;

    const int nc = K / GKC;

    issue_chunk(basep, K, 0, sbase, tid);
    CP_ASYNC_COMMIT();
    issue_chunk(basep, K, GKC, sbase + STAGEB, tid);
    CP_ASYNC_COMMIT();
    issue_chunk(basep, K, 2*GKC, sbase + 2*STAGEB, tid);
    CP_ASYNC_COMMIT();
    issue_chunk(basep, K, 3*GKC, sbase + 3*STAGEB, tid);
    CP_ASYNC_COMMIT();

    const uint32_t aOff = (uint32_t)((wm*64 + (lane & 15)) * (LDT*2) + (lane >> 4) * 16);
    const uint32_t bOff = (uint32_t)(TILEB +
        (wn*32 + (lane & 7) + ((lane >> 4) << 3)) * (LDT*2) + (((lane >> 3) & 1) * 16));

    for (int c = 0; c < nc; c++) {
        CP_ASYNC_WAIT3();
        __syncthreads();
        if (c + 4 < nc)
            issue_chunk(basep, K, (c + 4) * GKC, sbase + ((c + 4) % NSTAGE) * STAGEB, tid);
        CP_ASYNC_COMMIT();

        const uint32_t st = sbase + (c % NSTAGE) * STAGEB;
        #pragma unroll
        for (int ks = 0; ks < 2; ks++) {
            const uint32_t kb = ks * 32;
            uint32_t af[4][4], bf[2][4];
            #pragma unroll
            for (int mi = 0; mi < 4; mi++) {
                const uint32_t ah = st + aOff + mi * 16 * (LDT*2) + kb;
                LDSM_X4(af[mi][0], af[mi][1], af[mi][2], af[mi][3], ah);
            }
            #pragma unroll
            for (int p = 0; p < 2; p++) {
                const uint32_t bh = st + bOff + p * 16 * (LDT*2) + kb;
                LDSM_X4(bf[p][0], bf[p][1], bf[p][2], bf[p][3], bh);
            }
            #pragma unroll
            for (int mi = 0; mi < 4; mi++)
                #pragma unroll
                for (int ni = 0; ni < 4; ni++) {
                    const int p = ni >> 1, q = (ni & 1) << 1;
                    MMA_F16(acc[mi][ni], af[mi], bf[p][q], bf[p][q+1]);
                }
        }
    }

    #pragma unroll
    for (int mi = 0; mi < 4; mi++) {
        const int r0 = m0 + wm*64 + mi*16 + (lane >> 2);
        #pragma unroll
        for (int ni = 0; ni < 4; ni++) {
            const int c0 = n0 + wn*32 + ni*8 + (lane & 3)*2;
            float b0 = 0.f, b1 = 0.f;
            if (bias) { b0 = bias[c0]; b1 = bias[c0 + 1]; }
            store2(C + (size_t)r0 * N + c0,       acc[mi][ni][0] + b0, acc[mi][ni][1] + b1);
            store2(C + (size_t)(r0 + 8) * N + c0, acc[mi][ni][2] + b0, acc[mi][ni][3] + b1);
        }
    }
}

// ---------------- RoPE apply + head split (8 pairs/thread) ----------------
__global__ __launch_bounds__(256) void rope_apply()
{
    const int total = MROWS * 36 * 8;
    int idx = blockIdx.x * 256 + threadIdx.x;
    if (idx >= total) return;
    const int i8 = idx & 7;
    const int h  = (idx >> 3) % 36;
    const int bs = idx / (36 * 8);
    const int b  = bs >> 11;
    const int s  = bs & 2047;
    const int i0 = i8 * 8;

    const __half* row = g_qkvh + (size_t)bs * NQKV + h * DH;
    uint4 xa = *(const uint4*)(row + i0);
    uint4 xb = *(const uint4*)(row + i0 + 64);
    float x1[8], x2[8];
    {
        const __half2* pa = reinterpret_cast<const __half2*>(&xa);
        const __half2* pb = reinterpret_cast<const __half2*>(&xb);
        #pragma unroll
        for (int j = 0; j < 4; j++) {
            x1[2*j]   = __low2float(pa[j]);  x1[2*j+1] = __high2float(pa[j]);
            x2[2*j]   = __low2float(pb[j]);  x2[2*j+1] = __high2float(pb[j]);
        }
    }

    float o1[8], o2[8];
    if (h < 32) {
        const float4 cv0 = *(const float4*)(g_cos + (size_t)bs*64 + i0);
        const float4 cv1 = *(const float4*)(g_cos + (size_t)bs*64 + i0 + 4);
        const float4 sv0 = *(const float4*)(g_sin + (size_t)bs*64 + i0);
        const float4 sv1 = *(const float4*)(g_sin + (size_t)bs*64 + i0 + 4);
        const float c[8]  = {cv0.x, cv0.y, cv0.z, cv0.w, cv1.x, cv1.y, cv1.z, cv1.w};
        const float sn[8] = {sv0.x, sv0.y, sv0.z, sv0.w, sv1.x, sv1.y, sv1.z, sv1.w};
        #pragma unroll
        for (int j = 0; j < 8; j++) {
            o1[j] = x1[j]*c[j] - x2[j]*sn[j];
            o2[j] = x2[j]*c[j] + x1[j]*sn[j];
        }
    } else {
        #pragma unroll
        for (int j = 0; j < 8; j++) { o1[j] = x1[j]; o2[j] = x2[j]; }
    }

    __half* dst;
    if (h < NQ)      dst = g_Qh + ((size_t)(b*NQ  + h)        * SEQ + s) * DH;
    else if (h < 32) dst = g_Kh + ((size_t)(b*NKV + (h - NQ)) * SEQ + s) * DH;
    else             dst = g_Vh + ((size_t)(b*NKV + (h - 32)) * SEQ + s) * DH;

    uint4 oa, ob;
    uint32_t* wa = reinterpret_cast<uint32_t*>(&oa);
    uint32_t* wb = reinterpret_cast<uint32_t*>(&ob);
    #pragma unroll
    for (int j = 0; j < 4; j++) {
        __half2 t1 = __floats2half2_rn(o1[2*j], o1[2*j+1]);
        __half2 t2 = __floats2half2_rn(o2[2*j], o2[2*j+1]);
        wa[j] = *reinterpret_cast<uint32_t*>(&t1);
        wb[j] = *reinterpret_cast<uint32_t*>(&t2);
    }
    *(uint4*)(dst + i0)      = oa;
    *(uint4*)(dst + i0 + 64) = ob;
}

// ---------------- tensor-core flash attention (KV tile 128) ----------------
#define FPITCH_B 272
#define Q_BYTES (128 * FPITCH_B)             // 34816
#define KVROWS 128
#define KVT_BYTES (KVROWS * FPITCH_B)        // 34816
#define KVBUF (2 * KVT_BYTES)                // K, V = 69632
#define FLASH_SMEM (Q_BYTES + 2*KVBUF)       // 174080 -> 1 CTA/SM

__device__ __forceinline__ void issue_kv(uint32_t dstbase,
    const __half* Kh, const __half* Vh, int kt, int tid)
{
    const size_t off = (size_t)kt * KVROWS * DH;
    const char* s0 = (const char*)(Kh + off);
    const char* s1 = (const char*)(Vh + off);
    #pragma unroll
    for (int i = tid; i < 2048; i += 256) {
        const int row = i >> 4, ch = i & 15;
        const uint32_t d = dstbase + row * FPITCH_B + ch * 16;
        const int soff = row * 256 + ch * 16;
        CP_ASYNC_16(d,             s0 + soff);
        CP_ASYNC_16(d + KVT_BYTES, s1 + soff);
    }
}

__global__ __launch_bounds__(256, 1) void flash_mma()
{
    extern __shared__ char fsm[];
    const uint32_t sb = smem_to_u32(fsm);
    const int tid = threadIdx.x, wid = tid >> 5, lane = tid & 31;
    const int qt = (int)gridDim.x - 1 - (int)blockIdx.x;
    const int h = blockIdx.y, b = blockIdx.z;
    const int kvh = h / GQA;
    const int qbase = qt * 128;

    const __half* Qh_g = g_Qh + ((size_t)(b*NQ + h)*SEQ + qbase)*DH;
    const size_t kvoff = (size_t)(b*NKV + kvh)*SEQ*DH;
    const __half* Kh_g = g_Kh + kvoff;
    const __half* Vh_g = g_Vh + kvoff;

    #pragma unroll
    for (int i = tid; i < 2048; i += 256) {
        const int row = i >> 4, ch = i & 15;
        CP_ASYNC_16(sb + row * FPITCH_B + ch * 16,
                    (const char*)(Qh_g + (size_t)row * DH) + ch * 16);
    }
    CP_ASYNC_COMMIT();

    const int nkt = qt + 1;
    issue_kv(sb + Q_BYTES, Kh_g, Vh_g, 0, tid);
    CP_ASYNC_COMMIT();
    if (nkt > 1)
        issue_kv(sb + Q_BYTES + KVBUF, Kh_g, Vh_g, 1, tid);
    CP_ASYNC_COMMIT();

    const uint32_t aoff = (uint32_t)((wid*16 + (lane & 15)) * FPITCH_B + (lane >> 4) * 16);
    uint32_t qf[8][4];
    CP_ASYNC_WAIT2();
    __syncthreads();
    #pragma unroll
    for (int ks = 0; ks < 8; ks++) {
        const uint32_t qa = sb + aoff + ks * 32;
        LDSM_X4(qf[ks][0], qf[ks][1], qf[ks][2], qf[ks][3], qa);
    }

    float oacc[16][4];
    #pragma unroll
    for (int nn = 0; nn < 16; nn++)
        #pragma unroll
        for (int j = 0; j < 4; j++) oacc[nn][j] = 0.f;
    float l0 = 0.f, l1 = 0.f;

    const uint32_t boff = (uint32_t)(((lane & 7) + ((lane >> 4) << 3)) * FPITCH_B + ((lane >> 3) & 1) * 16);
    const uint32_t voff = (uint32_t)((lane & 15) * FPITCH_B + (lane >> 4) * 16);
    const int gr0 = qbase + wid*16 + (lane >> 2);
    const int gr1 = gr0 + 8;

    for (int kt = 0; kt < nkt; kt++) {
        CP_ASYNC_WAIT1();
        __syncthreads();
        const uint32_t kb = sb + Q_BYTES + (kt & 1) * KVBUF;

        float sacc[16][4];
        #pragma unroll
        for (int j = 0; j < 16; j++)
            #pragma unroll
            for (int e = 0; e < 4; e++) sacc[j][e] = 0.f;

        #pragma unroll
        for (int ks = 0; ks < 8; ks++) {
            #pragma unroll
            for (int jj = 0; jj < 8; jj++) {
                uint32_t bh[4];
                const uint32_t ka = kb + boff + jj * (16 * FPITCH_B) + ks * 32;
                LDSM_X4(bh[0], bh[1], bh[2], bh[3], ka);
                MMA_F16(sacc[2*jj],   qf[ks], bh[0], bh[1]);
                MMA_F16(sacc[2*jj+1], qf[ks], bh[2], bh[3]);
            }
        }

        if (kt == nkt - 1) {
            #pragma unroll
            for (int j = 0; j < 16; j++) {
                const int c0 = kt*KVROWS + j*8 + (lane & 3)*2;
                sacc[j][0] = (c0     > gr0) ? -1e9f : sacc[j][0] * C_SCALE;
                sacc[j][1] = (c0 + 1 > gr0) ? -1e9f : sacc[j][1] * C_SCALE;
                sacc[j][2] = (c0     > gr1) ? -1e9f : sacc[j][2] * C_SCALE;
                sacc[j][3] = (c0 + 1 > gr1) ? -1e9f : sacc[j][3] * C_SCALE;
            }
        } else {
            #pragma unroll
            for (int j = 0; j < 16; j++)
                #pragma unroll
                for (int e = 0; e < 4; e++) sacc[j][e] *= C_SCALE;
        }

        #pragma unroll
        for (int j = 0; j < 16; j++) {
            float p0 = fexp2(sacc[j][0]);
            float p1 = fexp2(sacc[j][1]);
            float p2 = fexp2(sacc[j][2]);
            float p3 = fexp2(sacc[j][3]);
            sacc[j][0] = p0; sacc[j][1] = p1; sacc[j][2] = p2; sacc[j][3] = p3;
            l0 += p0 + p1; l1 += p2 + p3;
        }

        #pragma unroll
        for (int kp = 0; kp < 8; kp++) {
            uint32_t pa[4];
            __half2 t0 = __floats2half2_rn(sacc[2*kp][0],   sacc[2*kp][1]);
            __half2 t1 = __floats2half2_rn(sacc[2*kp][2],   sacc[2*kp][3]);
            __half2 t2 = __floats2half2_rn(sacc[2*kp+1][0], sacc[2*kp+1][1]);
            __half2 t3 = __floats2half2_rn(sacc[2*kp+1][2], sacc[2*kp+1][3]);
            pa[0] = *reinterpret_cast<uint32_t*>(&t0);
            pa[1] = *reinterpret_cast<uint32_t*>(&t1);
            pa[2] = *reinterpret_cast<uint32_t*>(&t2);
            pa[3] = *reinterpret_cast<uint32_t*>(&t3);
            #pragma unroll
            for (int nj = 0; nj < 8; nj++) {
                uint32_t vh[4];
                const uint32_t va = kb + KVT_BYTES + voff + kp * (16 * FPITCH_B) + nj * 32;
                LDSM_X4T(vh[0], vh[1], vh[2], vh[3], va);
                MMA_F16(oacc[2*nj],   pa, vh[0], vh[1]);
                MMA_F16(oacc[2*nj+1], pa, vh[2], vh[3]);
            }
        }

        __syncthreads();
        if (kt + 2 < nkt)
            issue_kv(sb + Q_BYTES + (kt & 1) * KVBUF, Kh_g, Vh_g, kt + 2, tid);
        CP_ASYNC_COMMIT();
    }

    l0 += __shfl_xor_sync(0xffffffffu, l0, 1);
    l0 += __shfl_xor_sync(0xffffffffu, l0, 2);
    l1 += __shfl_xor_sync(0xffffffffu, l1, 1);
    l1 += __shfl_xor_sync(0xffffffffu, l1, 2);
    const float inv0 = 1.f / l0;
    const float inv1 = 1.f / l1;
    const size_t rbase0 = (size_t)(b*SEQ + gr0) * QSZ + h*DH;
    const size_t rbase1 = (size_t)(b*SEQ + gr1) * QSZ + h*DH;
    #pragma unroll
    for (int nn = 0; nn < 16; nn++) {
        const int col = nn*8 + (lane & 3)*2;
        __half2 o0 = __floats2half2_rn(oacc[nn][0]*inv0, oacc[nn][1]*inv0);
        __half2 o1 = __floats2half2_rn(oacc[nn][2]*inv1, oacc[nn][3]*inv1);
        *(uint32_t*)(g_O + rbase0 + col) = *reinterpret_cast<uint32_t*>(&o0);
        *(uint32_t*)(g_O + rbase1 + col) = *reinterpret_cast<uint32_t*>(&o1);
    }
}

// ---------------- launcher ----------------
extern "C" void kernel_launch(void* const* d_in, const int* in_sizes, int n_in,
                              void* d_out, int out_size)
{
    const int*   positions = (const int*)  d_in[0];
    const float* hidden    = (const float*)d_in[1];
    const float* Wqkv      = (const float*)d_in[2];
    const float* bqkv      = (const float*)d_in[3];
    const float* Wo        = (const float*)d_in[4];
    float* out = (float*)d_out;

    __half *qkvh_p, *a_p, *wq, *wo, *o_p;
    cudaGetSymbolAddress((void**)&qkvh_p, g_qkvh);
    cudaGetSymbolAddress((void**)&a_p, g_A);
    cudaGetSymbolAddress((void**)&wq,  g_WqkvT);
    cudaGetSymbolAddress((void**)&wo,  g_WoT);
    cudaGetSymbolAddress((void**)&o_p, g_O);

    cudaFuncSetAttribute(gemm_f16<__half>, cudaFuncAttributeMaxDynamicSharedMemorySize, GEMM_SMEM);
    cudaFuncSetAttribute(gemm_f16<float>,  cudaFuncAttributeMaxDynamicSharedMemorySize, GEMM_SMEM);
    cudaFuncSetAttribute(flash_mma, cudaFuncAttributeMaxDynamicSharedMemorySize, FLASH_SMEM);

    // prep: freq, then one fused kernel for convert + transposes + rope table
    freq_init<<<1, 64>>>();
    prep_fused<<<PREP_BLOCKS, 256>>>(
        (const float4*)hidden, (__half2*)a_p, Wqkv, wq, Wo, wo, positions);

    // 1) QKV projection + bias -> fp16
    gemm_f16<__half><<<dim3(NQKV/128, MROWS/128), 256, GEMM_SMEM>>>(
        a_p, wq, bqkv, qkvh_p, MROWS, NQKV, HIDDEN);

    // 2) RoPE apply (table-based) + head split
    {
        const int total = MROWS * 36 * 8;
        rope_apply<<<(total + 255)/256, 256>>>();
    }

    // 3) tensor-core causal flash attention (writes g_O fp16)
    flash_mma<<<dim3(SEQ/128, NQ, BATCH), 256, FLASH_SMEM>>>();

    // 4) output projection -> fp32 out
    gemm_f16<float><<<dim3(HIDDEN/128, MROWS/128), 256, GEMM_SMEM>>>(
        o_p, wo, (const float*)nullptr, out, MROWS, HIDDEN, QSZ);
}